// round 1
// baseline (speedup 1.0000x reference)
#include <cuda_runtime.h>

#define NN 768
#define LL 8
#define HH 64
#define RR (NN*LL)       // 6144 rows, row index = i*LL + l
#define KK 4
#define TT 3
#define HOUT (RR*HH)     // 393216 floats of h-output before coord-output

// ---------------- scratch (device globals; no dynamic allocation) ------------
__device__ __align__(16) float g_q[RR*HH];
__device__ __align__(16) float g_k[RR*HH];
__device__ __align__(16) float g_v[RR*HH];
__device__ __align__(16) float g_cmv[RR*KK];
__device__ __align__(16) float g_sc[(size_t)LL*NN*NN];   // [l][i][j]

// ---------------- Kernel 1: fused q/k/v MLPs + coord MLP --------------------
// Block handles 32 rows. Shared: A(h) tile, weight, temp, v tile. All GEMMs:
// C[32][64] = relu(A[32][64] @ W[64][64] + b). Thread tile 2 rows x 4 cols.

__device__ __forceinline__ void gemm_tile32(
    const float* __restrict__ A_s,   // [32][64] shared, row-major
    const float* __restrict__ W_s,   // [64][64] shared, row-major
    const float* __restrict__ bias,  // [64] global
    float* Cs,                       // optional shared out [32][64]
    float* gout,                     // optional global out (row-major, 64 cols)
    int gr0, int tx, int ty)
{
    const int r0 = ty * 2, c0 = tx * 4;
    const float b0 = bias[c0+0], b1 = bias[c0+1], b2 = bias[c0+2], b3 = bias[c0+3];
    float a00=b0, a01=b1, a02=b2, a03=b3;
    float a10=b0, a11=b1, a12=b2, a13=b3;
#pragma unroll 16
    for (int kk = 0; kk < 64; kk++) {
        float4 w = *(const float4*)(W_s + kk*64 + c0);
        float x0 = A_s[(r0+0)*64 + kk];
        float x1 = A_s[(r0+1)*64 + kk];
        a00 += x0*w.x; a01 += x0*w.y; a02 += x0*w.z; a03 += x0*w.w;
        a10 += x1*w.x; a11 += x1*w.y; a12 += x1*w.z; a13 += x1*w.w;
    }
    a00 = fmaxf(a00, 0.f); a01 = fmaxf(a01, 0.f); a02 = fmaxf(a02, 0.f); a03 = fmaxf(a03, 0.f);
    a10 = fmaxf(a10, 0.f); a11 = fmaxf(a11, 0.f); a12 = fmaxf(a12, 0.f); a13 = fmaxf(a13, 0.f);
    if (Cs) {
        *(float4*)(Cs + (r0+0)*64 + c0) = make_float4(a00, a01, a02, a03);
        *(float4*)(Cs + (r0+1)*64 + c0) = make_float4(a10, a11, a12, a13);
    }
    if (gout) {
        *(float4*)(gout + (size_t)(gr0 + r0 + 0)*64 + c0) = make_float4(a00, a01, a02, a03);
        *(float4*)(gout + (size_t)(gr0 + r0 + 1)*64 + c0) = make_float4(a10, a11, a12, a13);
    }
}

__device__ __forceinline__ void loadW64(float* W_s, const float* __restrict__ w, int tid)
{
    for (int e = tid; e < 64*64; e += 256) W_s[e] = w[e];
}

__global__ __launch_bounds__(256) void mlp_kernel(
    const float* __restrict__ h,
    const float* __restrict__ wq1, const float* __restrict__ bq1,
    const float* __restrict__ wq2, const float* __restrict__ bq2,
    const float* __restrict__ wk1, const float* __restrict__ bk1,
    const float* __restrict__ wk2, const float* __restrict__ bk2,
    const float* __restrict__ wv1, const float* __restrict__ bv1,
    const float* __restrict__ wv2, const float* __restrict__ bv2,
    const float* __restrict__ wc1, const float* __restrict__ bc1,
    const float* __restrict__ wc2)
{
    __shared__ __align__(16) float h_s[32*64];
    __shared__ __align__(16) float W_s[64*64];
    __shared__ __align__(16) float T_s[32*64];
    __shared__ __align__(16) float V_s[32*64];

    const int tid = threadIdx.x;
    const int tx = tid & 15, ty = tid >> 4;
    const int gr0 = blockIdx.x * 32;

    for (int e = tid; e < 32*64; e += 256) h_s[e] = h[(size_t)gr0*64 + e];

    // ---- q ----
    loadW64(W_s, wq1, tid); __syncthreads();
    gemm_tile32(h_s, W_s, bq1, T_s, nullptr, gr0, tx, ty); __syncthreads();
    loadW64(W_s, wq2, tid); __syncthreads();
    gemm_tile32(T_s, W_s, bq2, nullptr, g_q, gr0, tx, ty); __syncthreads();
    // ---- k ----
    loadW64(W_s, wk1, tid); __syncthreads();
    gemm_tile32(h_s, W_s, bk1, T_s, nullptr, gr0, tx, ty); __syncthreads();
    loadW64(W_s, wk2, tid); __syncthreads();
    gemm_tile32(T_s, W_s, bk2, nullptr, g_k, gr0, tx, ty); __syncthreads();
    // ---- v ----
    loadW64(W_s, wv1, tid); __syncthreads();
    gemm_tile32(h_s, W_s, bv1, T_s, nullptr, gr0, tx, ty); __syncthreads();
    loadW64(W_s, wv2, tid); __syncthreads();
    gemm_tile32(T_s, W_s, bv2, V_s, g_v, gr0, tx, ty); __syncthreads();
    // ---- coord mlp on v ----
    loadW64(W_s, wc1, tid); __syncthreads();
    gemm_tile32(V_s, W_s, bc1, T_s, nullptr, gr0, tx, ty); __syncthreads();
    // cmv = T @ wc2   (64 -> 4, no bias, no relu)
    if (tid < 128) {
        int r = tid >> 2, k = tid & 3;
        float s = 0.f;
#pragma unroll 16
        for (int c = 0; c < 64; c++) s += T_s[r*64 + c] * wc2[c*4 + k];
        g_cmv[(size_t)(gr0 + r)*4 + k] = s;
    }
}

// ---------------- Kernel 2: scores[l][i][j] = <q_il, k_jl> ------------------
// 64x64 output tile per block; A = q tile (row-major), W = k^T tile [h][j].

__global__ __launch_bounds__(256) void score_kernel()
{
    __shared__ __align__(16) float A_s[64*64];   // q [i][h]
    __shared__ __align__(16) float W_s[64*68];   // kT [h][j], padded row 68
    const int tid = threadIdx.x;
    const int tx = tid & 15, ty = tid >> 4;
    const int gj0 = blockIdx.x * 64;
    const int gi0 = blockIdx.y * 64;
    const int l   = blockIdx.z;

    for (int e = tid; e < 64*64; e += 256) {
        int a = e >> 6, hh = e & 63;
        A_s[e] = g_q[((size_t)(gi0 + a)*LL + l)*64 + hh];
        W_s[hh*68 + a] = g_k[((size_t)(gj0 + a)*LL + l)*64 + hh];
    }
    __syncthreads();

    const int r0 = ty * 4, c0 = tx * 4;   // r = i, c = j
    float acc[4][4];
#pragma unroll
    for (int i = 0; i < 4; i++)
#pragma unroll
        for (int j = 0; j < 4; j++) acc[i][j] = 0.f;

#pragma unroll 8
    for (int kk = 0; kk < 64; kk++) {
        float4 w = *(const float4*)(W_s + kk*68 + c0);
#pragma unroll
        for (int i = 0; i < 4; i++) {
            float a = A_s[(r0+i)*64 + kk];
            acc[i][0] += a*w.x; acc[i][1] += a*w.y; acc[i][2] += a*w.z; acc[i][3] += a*w.w;
        }
    }
#pragma unroll
    for (int i = 0; i < 4; i++) {
        *(float4*)&g_sc[((size_t)l*NN + gi0 + r0 + i)*NN + gj0 + c0] =
            make_float4(acc[i][0], acc[i][1], acc[i][2], acc[i][3]);
    }
}

// ---------------- Kernel 3: softmax over j, in place ------------------------

__global__ __launch_bounds__(256) void softmax_kernel()
{
    const int p = blockIdx.x;                // p = l*768 + i
    float* row = g_sc + (size_t)p * NN;
    const int tid = threadIdx.x;
    __shared__ float red[8];

    float x0 = row[tid], x1 = row[tid + 256], x2 = row[tid + 512];
    float m = fmaxf(fmaxf(x0, x1), x2);
#pragma unroll
    for (int o = 16; o; o >>= 1) m = fmaxf(m, __shfl_xor_sync(0xffffffffu, m, o));
    if ((tid & 31) == 0) red[tid >> 5] = m;
    __syncthreads();
    float M = red[0];
#pragma unroll
    for (int i = 1; i < 8; i++) M = fmaxf(M, red[i]);

    float e0 = __expf(x0 - M), e1 = __expf(x1 - M), e2 = __expf(x2 - M);
    float s = e0 + e1 + e2;
#pragma unroll
    for (int o = 16; o; o >>= 1) s += __shfl_xor_sync(0xffffffffu, s, o);
    __syncthreads();                          // red reads done before overwrite
    if ((tid & 31) == 0) red[tid >> 5] = s;
    __syncthreads();
    float S = 0.f;
#pragma unroll
    for (int i = 0; i < 8; i++) S += red[i];
    float inv = 1.0f / S;

    row[tid]       = e0 * inv;
    row[tid + 256] = e1 * inv;
    row[tid + 512] = e2 * inv;
}

// ---------------- Kernel 4: aggregation + epilogue --------------------------
// Per (32-row i-tile, l): C[32][80] = alpha[32][768] @ W[768][80]
// where W[j] = [ v(64) | cmv(4) | cmv*coord(12) ].
// Epilogue: h_out = h + C[:, :64];  coord_out = coord*(1+S) - P.

__global__ __launch_bounds__(256) void agg_kernel(
    const float* __restrict__ h_in,
    const float* __restrict__ coord,
    float* __restrict__ out)
{
    __shared__ __align__(16) float A_s[32*64];
    __shared__ __align__(16) float W_s[64*80];
    __shared__ float sp_s[32*16];

    const int tid = threadIdx.x;
    const int tx = tid & 15, ty = tid >> 4;
    const int gi0 = blockIdx.x * 32;
    const int l   = blockIdx.y;
    const int r0 = ty * 2, f0 = tx * 5;

    float acc[2][5];
#pragma unroll
    for (int i = 0; i < 2; i++)
#pragma unroll
        for (int f = 0; f < 5; f++) acc[i][f] = 0.f;

    for (int jt = 0; jt < 12; jt++) {
        const int gj0 = jt * 64;
        for (int e = tid; e < 32*64; e += 256) {
            int i = e >> 6, j = e & 63;
            A_s[e] = g_sc[((size_t)l*NN + gi0 + i)*NN + gj0 + j];
        }
        for (int e = tid; e < 64*80; e += 256) {
            int j = e / 80, f = e % 80;
            size_t row = (size_t)(gj0 + j)*LL + l;
            float val;
            if (f < 64)      val = g_v[row*64 + f];
            else if (f < 68) val = g_cmv[row*4 + (f - 64)];
            else {
                int kt = f - 68;
                val = g_cmv[row*4 + kt/3] * coord[row*12 + kt];
            }
            W_s[e] = val;
        }
        __syncthreads();

#pragma unroll 8
        for (int j = 0; j < 64; j++) {
            float a0 = A_s[(r0+0)*64 + j];
            float a1 = A_s[(r0+1)*64 + j];
#pragma unroll
            for (int ff = 0; ff < 5; ff++) {
                float w = W_s[j*80 + f0 + ff];
                acc[0][ff] += a0 * w;
                acc[1][ff] += a1 * w;
            }
        }
        __syncthreads();
    }

    // epilogue
#pragma unroll
    for (int i = 0; i < 2; i++) {
        size_t row = (size_t)(gi0 + r0 + i)*LL + l;
#pragma unroll
        for (int ff = 0; ff < 5; ff++) {
            int f = f0 + ff;
            if (f < 64) out[row*64 + f] = h_in[row*64 + f] + acc[i][ff];
            else        sp_s[(r0 + i)*16 + (f - 64)] = acc[i][ff];
        }
    }
    __syncthreads();
    for (int e = tid; e < 32*12; e += 256) {
        int r = e / 12, kt = e % 12, k = kt / 3;
        size_t row = (size_t)(gi0 + r)*LL + l;
        float c = coord[row*12 + kt];
        out[HOUT + row*12 + kt] = c + c * sp_s[r*16 + k] - sp_s[r*16 + 4 + kt];
    }
}

// ---------------- launch -----------------------------------------------------

extern "C" void kernel_launch(void* const* d_in, const int* in_sizes, int n_in,
                              void* d_out, int out_size)
{
    const float* h     = (const float*)d_in[0];
    const float* coord = (const float*)d_in[1];
    const float* wq1 = (const float*)d_in[2];  const float* bq1 = (const float*)d_in[3];
    const float* wq2 = (const float*)d_in[4];  const float* bq2 = (const float*)d_in[5];
    const float* wk1 = (const float*)d_in[6];  const float* bk1 = (const float*)d_in[7];
    const float* wk2 = (const float*)d_in[8];  const float* bk2 = (const float*)d_in[9];
    const float* wv1 = (const float*)d_in[10]; const float* bv1 = (const float*)d_in[11];
    const float* wv2 = (const float*)d_in[12]; const float* bv2 = (const float*)d_in[13];
    const float* wc1 = (const float*)d_in[14]; const float* bc1 = (const float*)d_in[15];
    const float* wc2 = (const float*)d_in[16];
    float* out = (float*)d_out;

    mlp_kernel<<<RR/32, 256>>>(h, wq1, bq1, wq2, bq2, wk1, bk1, wk2, bk2,
                               wv1, bv1, wv2, bv2, wc1, bc1, wc2);
    score_kernel<<<dim3(NN/64, NN/64, LL), 256>>>();
    softmax_kernel<<<RR, 256>>>();
    agg_kernel<<<dim3(NN/32, LL), 256>>>(h, coord, out);
}

// round 9
// speedup vs baseline: 1.7204x; 1.7204x over previous
#include <cuda_runtime.h>

#define NN 768
#define LL 8
#define HH 64
#define RR (NN*LL)       // 6144 rows, row index = node*LL + l
#define KK 4
#define TT 3
#define FF 80            // features: 64 v | 4 cmv | 12 cmv*coord
#define HOUT (RR*HH)     // h-output floats before coord-output

// ---------------- scratch (device globals; no dynamic allocation) ------------
__device__ __align__(16) float g_q[RR*HH];
__device__ __align__(16) float g_k[RR*HH];
__device__ __align__(16) float g_F[(size_t)LL*NN*FF];    // [l][j][80]
__device__ __align__(16) float g_sc[(size_t)LL*NN*NN];   // [l][i][j]
__device__ __align__(16) float g_part[(size_t)4*RR*FF];  // [js][row][80]

// ---------------- Kernel 1: fused q/k/v MLPs + coord MLP + F build ----------

__device__ __forceinline__ void gemm_tile32(
    const float* __restrict__ A_s,   // [32][64] shared
    const float* __restrict__ W_s,   // [64][64] shared
    const float* __restrict__ bias,
    float* Cs,                       // optional shared out [32][64]
    float* gout,                     // optional global out
    int gr0, int tx, int ty)
{
    const int r0 = ty * 2, c0 = tx * 4;
    const float b0 = bias[c0+0], b1 = bias[c0+1], b2 = bias[c0+2], b3 = bias[c0+3];
    float a00=b0, a01=b1, a02=b2, a03=b3;
    float a10=b0, a11=b1, a12=b2, a13=b3;
#pragma unroll 16
    for (int kk = 0; kk < 64; kk++) {
        float4 w = *(const float4*)(W_s + kk*64 + c0);
        float x0 = A_s[(r0+0)*64 + kk];
        float x1 = A_s[(r0+1)*64 + kk];
        a00 += x0*w.x; a01 += x0*w.y; a02 += x0*w.z; a03 += x0*w.w;
        a10 += x1*w.x; a11 += x1*w.y; a12 += x1*w.z; a13 += x1*w.w;
    }
    a00 = fmaxf(a00, 0.f); a01 = fmaxf(a01, 0.f); a02 = fmaxf(a02, 0.f); a03 = fmaxf(a03, 0.f);
    a10 = fmaxf(a10, 0.f); a11 = fmaxf(a11, 0.f); a12 = fmaxf(a12, 0.f); a13 = fmaxf(a13, 0.f);
    if (Cs) {
        *(float4*)(Cs + (r0+0)*64 + c0) = make_float4(a00, a01, a02, a03);
        *(float4*)(Cs + (r0+1)*64 + c0) = make_float4(a10, a11, a12, a13);
    }
    if (gout) {
        *(float4*)(gout + (size_t)(gr0 + r0 + 0)*64 + c0) = make_float4(a00, a01, a02, a03);
        *(float4*)(gout + (size_t)(gr0 + r0 + 1)*64 + c0) = make_float4(a10, a11, a12, a13);
    }
}

__device__ __forceinline__ void loadW64(float* W_s, const float* __restrict__ w, int tid)
{
    for (int e = tid; e < 64*64; e += 256) W_s[e] = w[e];
}

__global__ __launch_bounds__(256) void mlp_kernel(
    const float* __restrict__ h,
    const float* __restrict__ coord,
    const float* __restrict__ wq1, const float* __restrict__ bq1,
    const float* __restrict__ wq2, const float* __restrict__ bq2,
    const float* __restrict__ wk1, const float* __restrict__ bk1,
    const float* __restrict__ wk2, const float* __restrict__ bk2,
    const float* __restrict__ wv1, const float* __restrict__ bv1,
    const float* __restrict__ wv2, const float* __restrict__ bv2,
    const float* __restrict__ wc1, const float* __restrict__ bc1,
    const float* __restrict__ wc2)
{
    __shared__ __align__(16) float h_s[32*64];
    __shared__ __align__(16) float W_s[64*64];
    __shared__ __align__(16) float T_s[32*64];
    __shared__ __align__(16) float V_s[32*64];
    __shared__ float cmv_s[32*4];

    const int tid = threadIdx.x;
    const int tx = tid & 15, ty = tid >> 4;
    const int gr0 = blockIdx.x * 32;

    for (int e = tid; e < 32*64; e += 256) h_s[e] = h[(size_t)gr0*64 + e];

    // ---- q ----
    loadW64(W_s, wq1, tid); __syncthreads();
    gemm_tile32(h_s, W_s, bq1, T_s, nullptr, gr0, tx, ty); __syncthreads();
    loadW64(W_s, wq2, tid); __syncthreads();
    gemm_tile32(T_s, W_s, bq2, nullptr, g_q, gr0, tx, ty); __syncthreads();
    // ---- k ----
    loadW64(W_s, wk1, tid); __syncthreads();
    gemm_tile32(h_s, W_s, bk1, T_s, nullptr, gr0, tx, ty); __syncthreads();
    loadW64(W_s, wk2, tid); __syncthreads();
    gemm_tile32(T_s, W_s, bk2, nullptr, g_k, gr0, tx, ty); __syncthreads();
    // ---- v ----
    loadW64(W_s, wv1, tid); __syncthreads();
    gemm_tile32(h_s, W_s, bv1, T_s, nullptr, gr0, tx, ty); __syncthreads();
    loadW64(W_s, wv2, tid); __syncthreads();
    gemm_tile32(T_s, W_s, bv2, V_s, nullptr, gr0, tx, ty); __syncthreads();
    // ---- coord mlp hidden ----
    loadW64(W_s, wc1, tid); __syncthreads();
    gemm_tile32(V_s, W_s, bc1, T_s, nullptr, gr0, tx, ty); __syncthreads();
    // cmv = T @ wc2 (64 -> 4, no bias/relu)
    if (tid < 128) {
        int r = tid >> 2, k = tid & 3;
        float s = 0.f;
#pragma unroll 16
        for (int c = 0; c < 64; c++) s += T_s[r*64 + c] * wc2[c*4 + k];
        cmv_s[r*4 + k] = s;
    }
    __syncthreads();
    // ---- build F[l][node][80] = [v | cmv | cmv*coord] ----
    for (int e = tid; e < 32*FF; e += 256) {
        int r = e / FF, f = e % FF;
        int grow = gr0 + r;              // = node*LL + l
        int node = grow >> 3, l = grow & 7;
        float val;
        if (f < 64)      val = V_s[r*64 + f];
        else if (f < 68) val = cmv_s[r*4 + (f - 64)];
        else {
            int kt = f - 68;
            val = cmv_s[r*4 + kt/3] * coord[(size_t)grow*12 + kt];
        }
        g_F[((size_t)l*NN + node)*FF + f] = val;
    }
}

// ---------------- Kernel 2: scores[l][i][j] = <q_il, k_jl> ------------------

__global__ __launch_bounds__(256) void score_kernel()
{
    __shared__ __align__(16) float A_s[64*64];   // q [i][h]
    __shared__ __align__(16) float W_s[64*68];   // kT [h][j], padded 68
    const int tid = threadIdx.x;
    const int tx = tid & 15, ty = tid >> 4;
    const int gj0 = blockIdx.x * 64;
    const int gi0 = blockIdx.y * 64;
    const int l   = blockIdx.z;

    for (int e = tid; e < 64*64; e += 256) {
        int a = e >> 6, hh = e & 63;
        A_s[e] = g_q[((size_t)(gi0 + a)*LL + l)*64 + hh];
        W_s[hh*68 + a] = g_k[((size_t)(gj0 + a)*LL + l)*64 + hh];
    }
    __syncthreads();

    const int r0 = ty * 4, c0 = tx * 4;
    float acc[4][4];
#pragma unroll
    for (int i = 0; i < 4; i++)
#pragma unroll
        for (int j = 0; j < 4; j++) acc[i][j] = 0.f;

#pragma unroll 8
    for (int kk = 0; kk < 64; kk++) {
        float4 w = *(const float4*)(W_s + kk*68 + c0);
#pragma unroll
        for (int i = 0; i < 4; i++) {
            float a = A_s[(r0+i)*64 + kk];
            acc[i][0] += a*w.x; acc[i][1] += a*w.y; acc[i][2] += a*w.z; acc[i][3] += a*w.w;
        }
    }
#pragma unroll
    for (int i = 0; i < 4; i++) {
        *(float4*)&g_sc[((size_t)l*NN + gi0 + r0 + i)*NN + gj0 + c0] =
            make_float4(acc[i][0], acc[i][1], acc[i][2], acc[i][3]);
    }
}

// ---------------- Kernel 3: softmax over j, in place ------------------------

__global__ __launch_bounds__(256) void softmax_kernel()
{
    const int p = blockIdx.x;                // p = l*768 + i
    float* row = g_sc + (size_t)p * NN;
    const int tid = threadIdx.x;
    __shared__ float red[8];

    float x0 = row[tid], x1 = row[tid + 256], x2 = row[tid + 512];
    float m = fmaxf(fmaxf(x0, x1), x2);
#pragma unroll
    for (int o = 16; o; o >>= 1) m = fmaxf(m, __shfl_xor_sync(0xffffffffu, m, o));
    if ((tid & 31) == 0) red[tid >> 5] = m;
    __syncthreads();
    float M = red[0];
#pragma unroll
    for (int i = 1; i < 8; i++) M = fmaxf(M, red[i]);

    float e0 = __expf(x0 - M), e1 = __expf(x1 - M), e2 = __expf(x2 - M);
    float s = e0 + e1 + e2;
#pragma unroll
    for (int o = 16; o; o >>= 1) s += __shfl_xor_sync(0xffffffffu, s, o);
    __syncthreads();
    if ((tid & 31) == 0) red[tid >> 5] = s;
    __syncthreads();
    float S = 0.f;
#pragma unroll
    for (int i = 0; i < 8; i++) S += red[i];
    float inv = 1.0f / S;

    row[tid]       = e0 * inv;
    row[tid + 256] = e1 * inv;
    row[tid + 512] = e2 * inv;
}

// ---------------- Kernel 4: agg partials (split-j GEMM) ---------------------
// block: 32 i-rows x 80 f, one l, one of 4 j-splits (192 j each).
// threads 128: tx in [0,16) covers f = {4tx..4tx+3, 64+tx}; ty in [0,8) covers 4 rows.

__global__ __launch_bounds__(128) void agg_kernel()
{
    __shared__ __align__(16) float A_s[32*65];   // alpha [i][j], pad 65
    __shared__ __align__(16) float W_s[64*80];   // F tile [j][f]
    const int tid = threadIdx.x;
    const int tx = tid & 15, ty = tid >> 4;
    const int gi0 = blockIdx.x * 32;
    const int l   = blockIdx.y;
    const int js  = blockIdx.z;
    const int r0  = ty * 4;

    float acc[4][5];
#pragma unroll
    for (int r = 0; r < 4; r++)
#pragma unroll
        for (int f = 0; f < 5; f++) acc[r][f] = 0.f;

    for (int jt = 0; jt < 3; jt++) {
        const int gj0 = js * 192 + jt * 64;
        for (int e = tid; e < 32*64; e += 128) {
            int i = e >> 6, j = e & 63;
            A_s[i*65 + j] = g_sc[((size_t)l*NN + gi0 + i)*NN + gj0 + j];
        }
        {
            const float4* src = (const float4*)g_F + ((size_t)l*NN + gj0)*(FF/4);
            float4* dst = (float4*)W_s;
            for (int e = tid; e < 64*(FF/4); e += 128) dst[e] = src[e];
        }
        __syncthreads();

#pragma unroll 4
        for (int j = 0; j < 64; j++) {
            float4 w = *(const float4*)(W_s + j*FF + tx*4);
            float ws = W_s[j*FF + 64 + tx];
#pragma unroll
            for (int r = 0; r < 4; r++) {
                float a = A_s[(r0+r)*65 + j];
                acc[r][0] += a*w.x; acc[r][1] += a*w.y;
                acc[r][2] += a*w.z; acc[r][3] += a*w.w;
                acc[r][4] += a*ws;
            }
        }
        __syncthreads();
    }

#pragma unroll
    for (int r = 0; r < 4; r++) {
        size_t row = (size_t)(gi0 + r0 + r)*LL + l;
        float* p = g_part + ((size_t)js*RR + row)*FF;
        *(float4*)(p + tx*4) = make_float4(acc[r][0], acc[r][1], acc[r][2], acc[r][3]);
        p[64 + tx] = acc[r][4];
    }
}

// ---------------- Kernel 5: reduce partials + epilogue ----------------------
// one warp per row (row = node*LL + l); block = 8 rows.

__global__ __launch_bounds__(256) void reduce_kernel(
    const float* __restrict__ h_in,
    const float* __restrict__ coord,
    float* __restrict__ out)
{
    const int warp = threadIdx.x >> 5, lane = threadIdx.x & 31;
    const size_t row = (size_t)blockIdx.x * 8 + warp;
    const float* p0 = g_part + row * FF;

    float s1 = 0.f, s2 = 0.f, s3 = 0.f;
#pragma unroll
    for (int js = 0; js < 4; js++) {
        const float* p = p0 + (size_t)js * RR * FF;
        s1 += p[lane];
        s2 += p[32 + lane];
        if (lane < 16) s3 += p[64 + lane];
    }

    out[row*64 + lane]      = h_in[row*64 + lane]      + s1;
    out[row*64 + 32 + lane] = h_in[row*64 + 32 + lane] + s2;

    // coord epilogue: lane kt<12 needs S_k (lane kt/3) and P_kt (lane 4+kt)
    float S = __shfl_sync(0xffffffffu, s3, (lane / 3) & 3);
    float P = __shfl_sync(0xffffffffu, s3, (4 + lane) & 31);
    if (lane < 12) {
        float c = coord[row*12 + lane];
        out[HOUT + row*12 + lane] = fmaf(c, S, c) - P;
    }
}

// ---------------- launch -----------------------------------------------------

extern "C" void kernel_launch(void* const* d_in, const int* in_sizes, int n_in,
                              void* d_out, int out_size)
{
    const float* h     = (const float*)d_in[0];
    const float* coord = (const float*)d_in[1];
    const float* wq1 = (const float*)d_in[2];  const float* bq1 = (const float*)d_in[3];
    const float* wq2 = (const float*)d_in[4];  const float* bq2 = (const float*)d_in[5];
    const float* wk1 = (const float*)d_in[6];  const float* bk1 = (const float*)d_in[7];
    const float* wk2 = (const float*)d_in[8];  const float* bk2 = (const float*)d_in[9];
    const float* wv1 = (const float*)d_in[10]; const float* bv1 = (const float*)d_in[11];
    const float* wv2 = (const float*)d_in[12]; const float* bv2 = (const float*)d_in[13];
    const float* wc1 = (const float*)d_in[14]; const float* bc1 = (const float*)d_in[15];
    const float* wc2 = (const float*)d_in[16];
    float* out = (float*)d_out;

    mlp_kernel<<<RR/32, 256>>>(h, coord, wq1, bq1, wq2, bq2, wk1, bk1, wk2, bk2,
                               wv1, bv1, wv2, bv2, wc1, bc1, wc2);
    score_kernel<<<dim3(NN/64, NN/64, LL), 256>>>();
    softmax_kernel<<<RR, 256>>>();
    agg_kernel<<<dim3(NN/32, LL, 4), 128>>>();
    reduce_kernel<<<RR/8, 256>>>(h, coord, out);
}